// round 1
// baseline (speedup 1.0000x reference)
#include <cuda_runtime.h>
#include <cstdint>

// Problem constants (fixed shapes for this bench)
#define BB    2
#define NPTS  20000
#define MM    4096
#define SS    2
#define KK    25
#define JJ    64
#define CIN   8      // 2 xy + 6 feature channels
#define COUT  64
#define H0    128
#define H1    256
#define PTS   8      // points per block
#define NTHR  256

// Device scratch (static allocation — no cudaMalloc allowed)
__device__ __align__(16) float g_xf[BB * NPTS * 8];          // [b*N+n][8]
__device__ float g_convwT[CIN * KK * COUT];                  // [(c*25+k)*64 + o]
__device__ float g_w0T[128 * 128];                           // [c*128 + o]
__device__ float g_w1T[128 * 256];                           // [c*256 + o]

// ---------------------------------------------------------------------------
// Prep kernel: build gather table xf, transpose weights, copy new_xyz to out.
// ---------------------------------------------------------------------------
__global__ void prep_kernel(const float* __restrict__ xyz,
                            const float* __restrict__ feat,
                            const float* __restrict__ new_xyz,
                            const float* __restrict__ conv_w,
                            const float* __restrict__ w0,
                            const float* __restrict__ w1,
                            float* __restrict__ out) {
    int i = blockIdx.x * blockDim.x + threadIdx.x;

    if (i < BB * NPTS) {
        float* r = g_xf + (size_t)i * 8;
        r[0] = xyz[i * 3 + 0];
        r[1] = xyz[i * 3 + 1];
#pragma unroll
        for (int c = 0; c < 6; c++) r[2 + c] = feat[i * 6 + c];
    }
    if (i < COUT * CIN * KK) {          // 12800 : i = o*200 + (c*25+k)
        int o = i / 200;
        int r = i % 200;
        g_convwT[r * 64 + o] = conv_w[i];
    }
    if (i < 128 * 128) {                // mlp_w0 [o][c] -> [c][o]
        int o = i >> 7, c = i & 127;
        g_w0T[c * 128 + o] = w0[i];
    }
    if (i < 256 * 128) {                // mlp_w1 [o][c] -> [c][o]
        int o = i >> 7, c = i & 127;
        g_w1T[c * 256 + o] = w1[i];
    }
    if (i < BB * MM * 3) {              // new_xyz passthrough (first output)
        out[i] = new_xyz[i];
    }
}

// ---------------------------------------------------------------------------
// Main fused kernel: one block handles PTS points end-to-end.
// ---------------------------------------------------------------------------
__global__ __launch_bounds__(NTHR) void msnet_main_kernel(
    const float* __restrict__ new_xyz,
    const int*   __restrict__ idx,
    const float* __restrict__ weight,
    const float* __restrict__ conv_b,
    const float* __restrict__ mlp_b0,
    const float* __restrict__ mlp_b1,
    float* __restrict__ out) {

    __shared__ float s_nf[PTS][SS * KK][8];   // 12.8 KB  weighted-gather result
    __shared__ float s_x[PTS][128];           // conv outputs (concat 2 scales)
    __shared__ float s_h[PTS][128];           // mlp0 outputs
    __shared__ float s_part[PTS][128];        // half-sum exchange buffer

    const int tid  = threadIdx.x;
    const int warp = tid >> 5;
    const int lane = tid & 31;

    // ---------------- Phase A: gather + weighted sum over J ----------------
    // Item = (p, s, k). 2 lanes cooperate per gathered row (16B each -> one
    // 32B sector = one L1tex wavefront per row).
    {
        const int hf = lane & 1;      // which float4 half of the 8-ch row
        const int pr = lane >> 1;     // row subgroup 0..15

        for (int it = warp; it < PTS * SS * KK; it += 8) {
            const int p  = it / (SS * KK);
            const int sk = it - p * (SS * KK);
            const int s  = sk / KK;
            const int k  = sk - s * KK;
            const int pid = blockIdx.x * PTS + p;
            const int b   = pid >> 12;          // / MM
            const int m   = pid & (MM - 1);

            const size_t base =
                ((((size_t)s * BB + b) * MM + m) * KK + k) * JJ;

            const int   iv0 = idx[base + lane];
            const int   iv1 = idx[base + 32 + lane];
            const float wv0 = weight[base + lane];
            const float wv1 = weight[base + 32 + lane];

            float4 acc = make_float4(0.f, 0.f, 0.f, 0.f);
#pragma unroll
            for (int t4 = 0; t4 < 4; t4++) {
                const int j  = t4 * 16 + pr;          // row 0..63
                const int ij = __shfl_sync(0xffffffffu, (t4 < 2 ? iv0 : iv1), j & 31);
                const float wj = __shfl_sync(0xffffffffu, (t4 < 2 ? wv0 : wv1), j & 31);
                const float4 v = *reinterpret_cast<const float4*>(
                    g_xf + ((size_t)b * NPTS + ij) * 8 + hf * 4);
                acc.x = fmaf(wj, v.x, acc.x);
                acc.y = fmaf(wj, v.y, acc.y);
                acc.z = fmaf(wj, v.z, acc.z);
                acc.w = fmaf(wj, v.w, acc.w);
            }
            // reduce across the 16 row-subgroups (keep hf lanes separate)
#pragma unroll
            for (int msk = 2; msk < 32; msk <<= 1) {
                acc.x += __shfl_xor_sync(0xffffffffu, acc.x, msk);
                acc.y += __shfl_xor_sync(0xffffffffu, acc.y, msk);
                acc.z += __shfl_xor_sync(0xffffffffu, acc.z, msk);
                acc.w += __shfl_xor_sync(0xffffffffu, acc.w, msk);
            }
            if (lane < 2) {
                if (lane == 0) {   // channels 0,1 get center subtraction
                    const float cx = new_xyz[((size_t)b * MM + m) * 3 + 0];
                    const float cy = new_xyz[((size_t)b * MM + m) * 3 + 1];
                    acc.x -= cx;
                    acc.y -= cy;
                }
                *reinterpret_cast<float4*>(&s_nf[p][sk][hf * 4]) = acc;
            }
        }
    }
    __syncthreads();

    // ---------------- Phase B: conv (200 -> 64 per scale) + ReLU -----------
    {
        const int o  = tid & 63;
        const int sI = (tid >> 6) & 1;
        const int hf = tid >> 7;            // split channel range c<4 / c>=4
        float acc[PTS];
#pragma unroll
        for (int p = 0; p < PTS; p++) acc[p] = 0.f;

        for (int c = hf * 4; c < hf * 4 + 4; ++c) {
            for (int k = 0; k < KK; ++k) {
                const float w = g_convwT[(c * KK + k) * 64 + o];
#pragma unroll
                for (int p = 0; p < PTS; p++)
                    acc[p] = fmaf(w, s_nf[p][sI * KK + k][c], acc[p]);
            }
        }
        if (tid >= 128) {
#pragma unroll
            for (int p = 0; p < PTS; p++) s_part[p][tid - 128] = acc[p];
        }
        __syncthreads();
        if (tid < 128) {
            const float bias = conv_b[o];
#pragma unroll
            for (int p = 0; p < PTS; p++) {
                const float v = acc[p] + s_part[p][tid] + bias;
                s_x[p][sI * 64 + o] = fmaxf(v, 0.f);
            }
        }
        __syncthreads();
    }

    // ---------------- Phase C: mlp0 (128 -> 128) + ReLU --------------------
    {
        const int oc = tid & 127;
        const int hf = tid >> 7;            // split c range into halves
        float acc[PTS];
#pragma unroll
        for (int p = 0; p < PTS; p++) acc[p] = 0.f;

        for (int c = hf * 64; c < hf * 64 + 64; ++c) {
            const float w = g_w0T[c * 128 + oc];
#pragma unroll
            for (int p = 0; p < PTS; p++)
                acc[p] = fmaf(w, s_x[p][c], acc[p]);
        }
        if (tid >= 128) {
#pragma unroll
            for (int p = 0; p < PTS; p++) s_part[p][oc] = acc[p];
        }
        __syncthreads();
        if (tid < 128) {
            const float bias = mlp_b0[oc];
#pragma unroll
            for (int p = 0; p < PTS; p++)
                s_h[p][oc] = fmaxf(acc[p] + s_part[p][oc] + bias, 0.f);
        }
        __syncthreads();
    }

    // ---------------- Phase D: mlp1 (128 -> 256) + ReLU + store ------------
    {
        float acc[PTS];
#pragma unroll
        for (int p = 0; p < PTS; p++) acc[p] = 0.f;

        for (int c = 0; c < 128; ++c) {
            const float w = g_w1T[c * 256 + tid];
#pragma unroll
            for (int p = 0; p < PTS; p++)
                acc[p] = fmaf(w, s_h[p][c], acc[p]);
        }
        const float bias = mlp_b1[tid];
        const size_t ob = (size_t)BB * MM * 3;
#pragma unroll
        for (int p = 0; p < PTS; p++) {
            const int pid = blockIdx.x * PTS + p;
            out[ob + (size_t)pid * 256 + tid] = fmaxf(acc[p] + bias, 0.f);
        }
    }
}

// ---------------------------------------------------------------------------
extern "C" void kernel_launch(void* const* d_in, const int* in_sizes, int n_in,
                              void* d_out, int out_size) {
    const float* xyz     = (const float*)d_in[0];
    const float* feature = (const float*)d_in[1];
    const float* new_xyz = (const float*)d_in[2];
    const int*   idx     = (const int*)  d_in[3];
    const float* weight  = (const float*)d_in[4];
    const float* conv_w  = (const float*)d_in[5];
    const float* conv_b  = (const float*)d_in[6];
    const float* mlp_w0  = (const float*)d_in[7];
    const float* mlp_b0  = (const float*)d_in[8];
    const float* mlp_w1  = (const float*)d_in[9];
    const float* mlp_b1  = (const float*)d_in[10];
    float* out = (float*)d_out;

    (void)in_sizes; (void)n_in; (void)out_size;

    // Prep: xf table (40000 rows), weight transposes, new_xyz copy.
    prep_kernel<<<(BB * NPTS + NTHR - 1) / NTHR, NTHR>>>(
        xyz, feature, new_xyz, conv_w, mlp_w0, mlp_w1, out);

    // Main fused kernel: 8192 points / PTS per block.
    msnet_main_kernel<<<(BB * MM) / PTS, NTHR>>>(
        new_xyz, idx, weight, conv_b, mlp_b0, mlp_b1, out);
}

// round 2
// speedup vs baseline: 1.0681x; 1.0681x over previous
#include <cuda_runtime.h>
#include <cstdint>

// Fixed shapes
#define BB    2
#define NPTS  20000
#define MM    4096
#define SS    2
#define KK    25
#define JJ    64
#define PTS   16     // points per block
#define NTHR  256

// Static device scratch
__device__ __align__(16) float g_xf[BB * NPTS * 8];     // gather table [b*N+n][8]
__device__ __align__(16) float g_cwP[KK * 2 * 64 * 4];  // conv w: [(k*2+c4)*64+o][4cc]
__device__ __align__(16) float g_w0P[32 * 128 * 4];     // mlp0 w: [(c4*128+o)][4cc]
__device__ __align__(16) float g_w1P[32 * 256 * 4];     // mlp1 w: [(c4*256+o)][4cc]
__device__ float g_wsum[64 * 2];                        // sum_k conv_w[o][c][k], c in {0,1}

// ---------------------------------------------------------------------------
// Prep: build xf table, pack weights into float4-friendly layouts,
// precompute center-fold sums, copy new_xyz to output head.
// ---------------------------------------------------------------------------
__global__ void prep_kernel(const float* __restrict__ xyz,
                            const float* __restrict__ feat,
                            const float* __restrict__ new_xyz,
                            const float* __restrict__ conv_w,
                            const float* __restrict__ w0,
                            const float* __restrict__ w1,
                            float* __restrict__ out) {
    int i = blockIdx.x * blockDim.x + threadIdx.x;

    if (i < BB * NPTS) {
        float* r = g_xf + (size_t)i * 8;
        r[0] = xyz[i * 3 + 0];
        r[1] = xyz[i * 3 + 1];
#pragma unroll
        for (int c = 0; c < 6; c++) r[2 + c] = feat[i * 6 + c];
    }
    if (i < KK * 2 * 64 * 4) {          // 12800: i = ((k*2+c4)*64+o)*4+cc
        int cc = i & 3;
        int o  = (i >> 2) & 63;
        int t  = i >> 8;
        int c4 = t & 1;
        int k  = t >> 1;
        g_cwP[i] = conv_w[o * 200 + (c4 * 4 + cc) * 25 + k];
    }
    if (i < 32 * 128 * 4) {             // 16384: i = (c4*128+o)*4+cc
        int cc = i & 3;
        int o  = (i >> 2) & 127;
        int c4 = i >> 9;
        g_w0P[i] = w0[o * 128 + c4 * 4 + cc];
    }
    if (i < 32 * 256 * 4) {             // 32768: i = (c4*256+o)*4+cc
        int cc = i & 3;
        int o  = (i >> 2) & 255;
        int c4 = i >> 10;
        g_w1P[i] = w1[o * 128 + c4 * 4 + cc];
    }
    if (i < 128) {                      // wsum[o][c] = sum_k conv_w[o][c][k]
        int o = i >> 1, c = i & 1;
        float s = 0.f;
#pragma unroll
        for (int k = 0; k < KK; k++) s += conv_w[o * 200 + c * 25 + k];
        g_wsum[i] = s;                  // i == o*2+c
    }
    if (i < BB * MM * 3) {              // new_xyz passthrough
        out[i] = new_xyz[i];
    }
}

// ---------------------------------------------------------------------------
// Main fused kernel: one block handles PTS=16 points end-to-end.
// ---------------------------------------------------------------------------
__global__ __launch_bounds__(NTHR) void msnet_main_kernel(
    const float* __restrict__ new_xyz,
    const int*   __restrict__ idx,
    const float* __restrict__ weight,
    const float* __restrict__ conv_b,
    const float* __restrict__ mlp_b0,
    const float* __restrict__ mlp_b1,
    float* __restrict__ out) {

    __shared__ __align__(16) float s_buf[PTS * 50 * 8]; // nf (phase A/B), then h (C/D)
    __shared__ __align__(16) float s_x[PTS * 128];      // conv outputs
    __shared__ float s_c[PTS * 2];                      // centers (xy)

    const int tid  = threadIdx.x;
    const int warp = tid >> 5;
    const int lane = tid & 31;
    const int blk  = blockIdx.x;

    if (tid < PTS * 2) {
        int p = tid >> 1, c = tid & 1;
        s_c[tid] = new_xyz[(size_t)(blk * PTS + p) * 3 + c];
    }

    // ---------------- Phase A: gather + weighted sum over J ----------------
    {
        const int hf = lane & 1;     // which 16B half of the 32B row
        const int pr = lane >> 1;    // row subgroup 0..15
        float4* s_nf4 = (float4*)s_buf;

        for (int it = warp; it < PTS * 50; it += 8) {
            const int p  = it / 50;
            const int sk = it - p * 50;
            const int s  = sk / 25;
            const int k  = sk - s * 25;
            const int pid = blk * PTS + p;
            const int b   = pid >> 12;
            const int m   = pid & (MM - 1);

            const size_t base =
                ((((size_t)s * BB + b) * MM + m) * KK + k) * JJ;

            const int   iv0 = idx[base + lane];
            const int   iv1 = idx[base + 32 + lane];
            const float wv0 = weight[base + lane];
            const float wv1 = weight[base + 32 + lane];

            float4 acc = make_float4(0.f, 0.f, 0.f, 0.f);
#pragma unroll
            for (int t4 = 0; t4 < 4; t4++) {
                const int j  = t4 * 16 + pr;
                const int   ij = __shfl_sync(0xffffffffu, (t4 < 2 ? iv0 : iv1), j & 31);
                const float wj = __shfl_sync(0xffffffffu, (t4 < 2 ? wv0 : wv1), j & 31);
                const float4 v = *reinterpret_cast<const float4*>(
                    g_xf + ((size_t)b * NPTS + ij) * 8 + hf * 4);
                acc.x = fmaf(wj, v.x, acc.x);
                acc.y = fmaf(wj, v.y, acc.y);
                acc.z = fmaf(wj, v.z, acc.z);
                acc.w = fmaf(wj, v.w, acc.w);
            }
#pragma unroll
            for (int msk = 2; msk < 32; msk <<= 1) {
                acc.x += __shfl_xor_sync(0xffffffffu, acc.x, msk);
                acc.y += __shfl_xor_sync(0xffffffffu, acc.y, msk);
                acc.z += __shfl_xor_sync(0xffffffffu, acc.z, msk);
                acc.w += __shfl_xor_sync(0xffffffffu, acc.w, msk);
            }
            if (lane < 2) {
                s_nf4[it * 2 + hf] = acc;
            }
        }
    }
    __syncthreads();

    // ------------- Phase B: conv 200->64 per scale, reg-tiled --------------
    // Thread tile: 1 output o, both scales, 4 points.
    {
        const int o  = lane + (warp & 1) * 32;   // 0..63
        const int pq = warp >> 1;                // 0..3
        const float4* cw4 = (const float4*)g_cwP;
        const float4* nf4 = (const float4*)s_buf;

        const float ws0 = g_wsum[o * 2 + 0];
        const float ws1 = g_wsum[o * 2 + 1];
        const float cb  = conv_b[o];

        float acc[SS][4];
#pragma unroll
        for (int pp = 0; pp < 4; pp++) {
            const float cx = s_c[(pq * 4 + pp) * 2 + 0];
            const float cy = s_c[(pq * 4 + pp) * 2 + 1];
            const float init = cb - ws0 * cx - ws1 * cy;  // center-fold
            acc[0][pp] = init;
            acc[1][pp] = init;
        }

        for (int k = 0; k < KK; k++) {
            const float4 wlo = cw4[(k * 2 + 0) * 64 + o];
            const float4 whi = cw4[(k * 2 + 1) * 64 + o];
#pragma unroll
            for (int s = 0; s < SS; s++) {
#pragma unroll
                for (int pp = 0; pp < 4; pp++) {
                    const int p = pq * 4 + pp;
                    const float4 alo = nf4[(p * 50 + s * 25 + k) * 2 + 0];
                    const float4 ahi = nf4[(p * 50 + s * 25 + k) * 2 + 1];
                    float a = acc[s][pp];
                    a = fmaf(wlo.x, alo.x, a);
                    a = fmaf(wlo.y, alo.y, a);
                    a = fmaf(wlo.z, alo.z, a);
                    a = fmaf(wlo.w, alo.w, a);
                    a = fmaf(whi.x, ahi.x, a);
                    a = fmaf(whi.y, ahi.y, a);
                    a = fmaf(whi.z, ahi.z, a);
                    a = fmaf(whi.w, ahi.w, a);
                    acc[s][pp] = a;
                }
            }
        }
#pragma unroll
        for (int s = 0; s < SS; s++)
#pragma unroll
            for (int pp = 0; pp < 4; pp++)
                s_x[(pq * 4 + pp) * 128 + s * 64 + o] = fmaxf(acc[s][pp], 0.f);
    }
    __syncthreads();

    // ------------- Phase C: mlp0 128->128, reg-tiled (1o x 8p) -------------
    {
        const int o  = lane + (warp & 3) * 32;   // 0..127
        const int p0 = (warp >> 2) * 8;          // 0 or 8
        const float4* w4 = (const float4*)g_w0P;
        const float4* x4 = (const float4*)s_x;

        float acc[8];
        const float b = mlp_b0[o];
#pragma unroll
        for (int pp = 0; pp < 8; pp++) acc[pp] = b;

        for (int c4 = 0; c4 < 32; c4++) {
            const float4 wv = w4[c4 * 128 + o];
#pragma unroll
            for (int pp = 0; pp < 8; pp++) {
                const float4 a = x4[(p0 + pp) * 32 + c4];
                float t = acc[pp];
                t = fmaf(wv.x, a.x, t);
                t = fmaf(wv.y, a.y, t);
                t = fmaf(wv.z, a.z, t);
                t = fmaf(wv.w, a.w, t);
                acc[pp] = t;
            }
        }
        __syncthreads();   // all s_buf (nf) reads finished in B; safe to overwrite
#pragma unroll
        for (int pp = 0; pp < 8; pp++)
            s_buf[(p0 + pp) * 128 + o] = fmaxf(acc[pp], 0.f);
    }
    __syncthreads();

    // ------------- Phase D: mlp1 128->256, reg-tiled (2o x 8p) -------------
    {
        const int o  = lane + (warp & 3) * 32;   // 0..127 (second output o+128)
        const int p0 = (warp >> 2) * 8;
        const float4* w4 = (const float4*)g_w1P;
        const float4* h4 = (const float4*)s_buf;

        float acc0[8], acc1[8];
        const float ba = mlp_b1[o];
        const float bb = mlp_b1[o + 128];
#pragma unroll
        for (int pp = 0; pp < 8; pp++) { acc0[pp] = ba; acc1[pp] = bb; }

        for (int c4 = 0; c4 < 32; c4++) {
            const float4 wa = w4[c4 * 256 + o];
            const float4 wb = w4[c4 * 256 + o + 128];
#pragma unroll
            for (int pp = 0; pp < 8; pp++) {
                const float4 a = h4[(p0 + pp) * 32 + c4];
                float t0 = acc0[pp];
                float t1 = acc1[pp];
                t0 = fmaf(wa.x, a.x, t0);
                t1 = fmaf(wb.x, a.x, t1);
                t0 = fmaf(wa.y, a.y, t0);
                t1 = fmaf(wb.y, a.y, t1);
                t0 = fmaf(wa.z, a.z, t0);
                t1 = fmaf(wb.z, a.z, t1);
                t0 = fmaf(wa.w, a.w, t0);
                t1 = fmaf(wb.w, a.w, t1);
                acc0[pp] = t0;
                acc1[pp] = t1;
            }
        }
        const size_t ob = (size_t)BB * MM * 3;
#pragma unroll
        for (int pp = 0; pp < 8; pp++) {
            const int pid = blk * PTS + p0 + pp;
            out[ob + (size_t)pid * 256 + o]       = fmaxf(acc0[pp], 0.f);
            out[ob + (size_t)pid * 256 + o + 128] = fmaxf(acc1[pp], 0.f);
        }
    }
}

// ---------------------------------------------------------------------------
extern "C" void kernel_launch(void* const* d_in, const int* in_sizes, int n_in,
                              void* d_out, int out_size) {
    const float* xyz     = (const float*)d_in[0];
    const float* feature = (const float*)d_in[1];
    const float* new_xyz = (const float*)d_in[2];
    const int*   idx     = (const int*)  d_in[3];
    const float* weight  = (const float*)d_in[4];
    const float* conv_w  = (const float*)d_in[5];
    const float* conv_b  = (const float*)d_in[6];
    const float* mlp_b0  = (const float*)d_in[8];
    const float* mlp_w0  = (const float*)d_in[7];
    const float* mlp_w1  = (const float*)d_in[9];
    const float* mlp_b1  = (const float*)d_in[10];
    float* out = (float*)d_out;

    (void)in_sizes; (void)n_in; (void)out_size;

    prep_kernel<<<(BB * NPTS + NTHR - 1) / NTHR, NTHR>>>(
        xyz, feature, new_xyz, conv_w, mlp_w0, mlp_w1, out);

    msnet_main_kernel<<<(BB * MM) / PTS, NTHR>>>(
        new_xyz, idx, weight, conv_b, mlp_b0, mlp_b1, out);
}

// round 3
// speedup vs baseline: 1.0814x; 1.0125x over previous
#include <cuda_runtime.h>
#include <cuda_fp16.h>
#include <cstdint>

// Fixed shapes
#define BB    2
#define NPTS  20000
#define MM    4096
#define SS    2
#define KK    25
#define JJ    64
#define PT    16     // points per gather block
#define PTS   16     // points per compute block
#define NTHR  256
#define GTHR  1024

// Static device scratch
__device__ __align__(16) __half g_xfh[BB * 2 * NPTS * 4]; // [b][chhalf][n][4ch] fp16
__device__ __align__(16) float  g_nf[BB * MM * 50 * 8];   // weighted-gather result
__device__ __align__(16) float  g_cwP[KK * 2 * 64 * 4];   // conv w packed
__device__ __align__(16) float  g_w0P[32 * 128 * 4];      // mlp0 w packed
__device__ __align__(16) float  g_w1P[32 * 256 * 4];      // mlp1 w packed
__device__ float g_wsum[64 * 2];                          // sum_k conv_w[o][c][k], c in {0,1}

// ---------------------------------------------------------------------------
// Prep: fp16 gather table (channel-split), packed weights, center-fold sums,
// new_xyz passthrough.
// ---------------------------------------------------------------------------
__global__ void prep_kernel(const float* __restrict__ xyz,
                            const float* __restrict__ feat,
                            const float* __restrict__ new_xyz,
                            const float* __restrict__ conv_w,
                            const float* __restrict__ w0,
                            const float* __restrict__ w1,
                            float* __restrict__ out) {
    int i = blockIdx.x * blockDim.x + threadIdx.x;

    if (i < BB * NPTS) {                 // build fp16 table, split in channel halves
        const int b = i / NPTS;
        const int n = i - b * NPTS;
        float c[8];
        c[0] = xyz[i * 3 + 0];
        c[1] = xyz[i * 3 + 1];
#pragma unroll
        for (int q = 0; q < 6; q++) c[2 + q] = feat[i * 6 + q];

        __half2* lo = reinterpret_cast<__half2*>(g_xfh + ((size_t)(b * 2 + 0) * NPTS + n) * 4);
        __half2* hi = reinterpret_cast<__half2*>(g_xfh + ((size_t)(b * 2 + 1) * NPTS + n) * 4);
        lo[0] = __floats2half2_rn(c[0], c[1]);
        lo[1] = __floats2half2_rn(c[2], c[3]);
        hi[0] = __floats2half2_rn(c[4], c[5]);
        hi[1] = __floats2half2_rn(c[6], c[7]);
    }
    if (i < KK * 2 * 64 * 4) {          // 12800: i = ((k*2+c4)*64+o)*4+cc
        int cc = i & 3;
        int o  = (i >> 2) & 63;
        int t  = i >> 8;
        int c4 = t & 1;
        int k  = t >> 1;
        g_cwP[i] = conv_w[o * 200 + (c4 * 4 + cc) * 25 + k];
    }
    if (i < 32 * 128 * 4) {             // i = (c4*128+o)*4+cc
        int cc = i & 3;
        int o  = (i >> 2) & 127;
        int c4 = i >> 9;
        g_w0P[i] = w0[o * 128 + c4 * 4 + cc];
    }
    if (i < 32 * 256 * 4) {             // i = (c4*256+o)*4+cc
        int cc = i & 3;
        int o  = (i >> 2) & 255;
        int c4 = i >> 10;
        g_w1P[i] = w1[o * 128 + c4 * 4 + cc];
    }
    if (i < 128) {                      // wsum[o][c] = sum_k conv_w[o][c][k]
        int o = i >> 1, c = i & 1;
        float s = 0.f;
#pragma unroll
        for (int k = 0; k < KK; k++) s += conv_w[o * 200 + c * 25 + k];
        g_wsum[i] = s;
    }
    if (i < BB * MM * 3) {              // new_xyz passthrough
        out[i] = new_xyz[i];
    }
}

// ---------------------------------------------------------------------------
// Gather kernel: table (4 fp16 channels, one batch) in smem; warp per item.
// blockIdx = (b, mtile, chhalf) with chhalf fastest (L2 twin dedup of idx/w).
// ---------------------------------------------------------------------------
__global__ __launch_bounds__(GTHR) void gather_kernel(
    const int*   __restrict__ idx,
    const float* __restrict__ weight) {

    extern __shared__ __align__(16) uint2 s_tab[];  // NPTS rows of 4×fp16

    const int tid = threadIdx.x;
    const int blk = blockIdx.x;
    const int ch  = blk & 1;                  // channel half
    const int mt  = (blk >> 1) & ((MM / PT) - 1);
    const int b   = blk >> 9;                 // (MM/PT)=256 tiles -> 9 bits incl ch

    // Load table half: 160 KB, coalesced
    const uint2* gt = reinterpret_cast<const uint2*>(g_xfh) + (size_t)(b * 2 + ch) * NPTS;
#pragma unroll 5
    for (int i = tid; i < NPTS; i += GTHR) s_tab[i] = gt[i];
    __syncthreads();

    const int warp = tid >> 5;
    const int lane = tid & 31;

    // Items: it in [0, PT*50). p = it/50, sk = it%50. 25 items per warp.
    int it = warp;
    int2   iv;
    float2 wv;
    {
        const int p = it / 50, sk = it - p * 50;
        const int s = sk / 25, k = sk - s * 25;
        const int m = mt * PT + p;
        const size_t base = ((((size_t)s * BB + b) * MM + m) * KK + k) * JJ;
        iv = reinterpret_cast<const int2*>(idx + base)[lane];
        wv = reinterpret_cast<const float2*>(weight + base)[lane];
    }

    for (int n = 0; n < PT * 50 / 32; n++) {
        const int   cit = it;
        const int2   civ = iv;
        const float2 cwv = wv;
        it += 32;
        if (n < PT * 50 / 32 - 1) {     // prefetch next item
            const int p = it / 50, sk = it - p * 50;
            const int s = sk / 25, k = sk - s * 25;
            const int m = mt * PT + p;
            const size_t base = ((((size_t)s * BB + b) * MM + m) * KK + k) * JJ;
            iv = reinterpret_cast<const int2*>(idx + base)[lane];
            wv = reinterpret_cast<const float2*>(weight + base)[lane];
        }

        // Gather two rows from smem (random 8B loads)
        uint2 r0 = s_tab[civ.x];
        uint2 r1 = s_tab[civ.y];
        const __half2* h0 = reinterpret_cast<const __half2*>(&r0);
        const __half2* h1 = reinterpret_cast<const __half2*>(&r1);
        float2 f00 = __half22float2(h0[0]);
        float2 f01 = __half22float2(h0[1]);
        float2 f10 = __half22float2(h1[0]);
        float2 f11 = __half22float2(h1[1]);

        float a0 = fmaf(cwv.x, f00.x, cwv.y * f10.x);
        float a1 = fmaf(cwv.x, f00.y, cwv.y * f10.y);
        float a2 = fmaf(cwv.x, f01.x, cwv.y * f11.x);
        float a3 = fmaf(cwv.x, f01.y, cwv.y * f11.y);

#pragma unroll
        for (int msk = 16; msk >= 1; msk >>= 1) {
            a0 += __shfl_xor_sync(0xffffffffu, a0, msk);
            a1 += __shfl_xor_sync(0xffffffffu, a1, msk);
            a2 += __shfl_xor_sync(0xffffffffu, a2, msk);
            a3 += __shfl_xor_sync(0xffffffffu, a3, msk);
        }
        if (lane == 0) {
            const int p = cit / 50, sk = cit - p * 50;
            const int pid = b * MM + mt * PT + p;
            *reinterpret_cast<float4*>(
                g_nf + ((size_t)pid * 50 + sk) * 8 + ch * 4) =
                make_float4(a0, a1, a2, a3);
        }
    }
}

// ---------------------------------------------------------------------------
// Compute kernel: conv + mlp0 + mlp1 (R2-proven), nf read from global.
// ---------------------------------------------------------------------------
__global__ __launch_bounds__(NTHR) void compute_kernel(
    const float* __restrict__ new_xyz,
    const float* __restrict__ conv_b,
    const float* __restrict__ mlp_b0,
    const float* __restrict__ mlp_b1,
    float* __restrict__ out) {

    __shared__ __align__(16) float s_buf[PTS * 50 * 8]; // nf, later mlp0 out
    __shared__ __align__(16) float s_x[PTS * 128];      // conv outputs
    __shared__ float s_c[PTS * 2];                      // centers (xy)

    const int tid  = threadIdx.x;
    const int warp = tid >> 5;
    const int lane = tid & 31;
    const int blk  = blockIdx.x;

    if (tid < PTS * 2) {
        int p = tid >> 1, c = tid & 1;
        s_c[tid] = new_xyz[(size_t)(blk * PTS + p) * 3 + c];
    }

    // Load nf tile (coalesced)
    {
        float4* sb4 = reinterpret_cast<float4*>(s_buf);
        const float4* g4 = reinterpret_cast<const float4*>(g_nf) + (size_t)blk * (PTS * 100);
        for (int i = tid; i < PTS * 100; i += NTHR) sb4[i] = g4[i];
    }
    __syncthreads();

    // ------------- Phase B: conv 200->64 per scale, reg-tiled --------------
    {
        const int o  = lane + (warp & 1) * 32;   // 0..63
        const int pq = warp >> 1;                // 0..3
        const float4* cw4 = (const float4*)g_cwP;
        const float4* nf4 = (const float4*)s_buf;

        const float ws0 = g_wsum[o * 2 + 0];
        const float ws1 = g_wsum[o * 2 + 1];
        const float cb  = conv_b[o];

        float acc[SS][4];
#pragma unroll
        for (int pp = 0; pp < 4; pp++) {
            const float cx = s_c[(pq * 4 + pp) * 2 + 0];
            const float cy = s_c[(pq * 4 + pp) * 2 + 1];
            const float init = cb - ws0 * cx - ws1 * cy;  // center-fold
            acc[0][pp] = init;
            acc[1][pp] = init;
        }

        for (int k = 0; k < KK; k++) {
            const float4 wlo = cw4[(k * 2 + 0) * 64 + o];
            const float4 whi = cw4[(k * 2 + 1) * 64 + o];
#pragma unroll
            for (int s = 0; s < SS; s++) {
#pragma unroll
                for (int pp = 0; pp < 4; pp++) {
                    const int p = pq * 4 + pp;
                    const float4 alo = nf4[(p * 50 + s * 25 + k) * 2 + 0];
                    const float4 ahi = nf4[(p * 50 + s * 25 + k) * 2 + 1];
                    float a = acc[s][pp];
                    a = fmaf(wlo.x, alo.x, a);
                    a = fmaf(wlo.y, alo.y, a);
                    a = fmaf(wlo.z, alo.z, a);
                    a = fmaf(wlo.w, alo.w, a);
                    a = fmaf(whi.x, ahi.x, a);
                    a = fmaf(whi.y, ahi.y, a);
                    a = fmaf(whi.z, ahi.z, a);
                    a = fmaf(whi.w, ahi.w, a);
                    acc[s][pp] = a;
                }
            }
        }
#pragma unroll
        for (int s = 0; s < SS; s++)
#pragma unroll
            for (int pp = 0; pp < 4; pp++)
                s_x[(pq * 4 + pp) * 128 + s * 64 + o] = fmaxf(acc[s][pp], 0.f);
    }
    __syncthreads();

    // ------------- Phase C: mlp0 128->128, reg-tiled (1o x 8p) -------------
    {
        const int o  = lane + (warp & 3) * 32;   // 0..127
        const int p0 = (warp >> 2) * 8;          // 0 or 8
        const float4* w4 = (const float4*)g_w0P;
        const float4* x4 = (const float4*)s_x;

        float acc[8];
        const float b = mlp_b0[o];
#pragma unroll
        for (int pp = 0; pp < 8; pp++) acc[pp] = b;

        for (int c4 = 0; c4 < 32; c4++) {
            const float4 wvv = w4[c4 * 128 + o];
#pragma unroll
            for (int pp = 0; pp < 8; pp++) {
                const float4 a = x4[(p0 + pp) * 32 + c4];
                float t = acc[pp];
                t = fmaf(wvv.x, a.x, t);
                t = fmaf(wvv.y, a.y, t);
                t = fmaf(wvv.z, a.z, t);
                t = fmaf(wvv.w, a.w, t);
                acc[pp] = t;
            }
        }
        __syncthreads();   // all s_buf (nf) reads finished; safe to overwrite
#pragma unroll
        for (int pp = 0; pp < 8; pp++)
            s_buf[(p0 + pp) * 128 + o] = fmaxf(acc[pp], 0.f);
    }
    __syncthreads();

    // ------------- Phase D: mlp1 128->256, reg-tiled (2o x 8p) -------------
    {
        const int o  = lane + (warp & 3) * 32;   // 0..127 (+128 second half)
        const int p0 = (warp >> 2) * 8;
        const float4* w4 = (const float4*)g_w1P;
        const float4* h4 = (const float4*)s_buf;

        float acc0[8], acc1[8];
        const float ba = mlp_b1[o];
        const float bb = mlp_b1[o + 128];
#pragma unroll
        for (int pp = 0; pp < 8; pp++) { acc0[pp] = ba; acc1[pp] = bb; }

        for (int c4 = 0; c4 < 32; c4++) {
            const float4 wa = w4[c4 * 256 + o];
            const float4 wb = w4[c4 * 256 + o + 128];
#pragma unroll
            for (int pp = 0; pp < 8; pp++) {
                const float4 a = h4[(p0 + pp) * 32 + c4];
                float t0 = acc0[pp];
                float t1 = acc1[pp];
                t0 = fmaf(wa.x, a.x, t0);
                t1 = fmaf(wb.x, a.x, t1);
                t0 = fmaf(wa.y, a.y, t0);
                t1 = fmaf(wb.y, a.y, t1);
                t0 = fmaf(wa.z, a.z, t0);
                t1 = fmaf(wb.z, a.z, t1);
                t0 = fmaf(wa.w, a.w, t0);
                t1 = fmaf(wb.w, a.w, t1);
                acc0[pp] = t0;
                acc1[pp] = t1;
            }
        }
        const size_t ob = (size_t)BB * MM * 3;
#pragma unroll
        for (int pp = 0; pp < 8; pp++) {
            const int pid = blk * PTS + p0 + pp;
            out[ob + (size_t)pid * 256 + o]       = fmaxf(acc0[pp], 0.f);
            out[ob + (size_t)pid * 256 + o + 128] = fmaxf(acc1[pp], 0.f);
        }
    }
}

// ---------------------------------------------------------------------------
extern "C" void kernel_launch(void* const* d_in, const int* in_sizes, int n_in,
                              void* d_out, int out_size) {
    const float* xyz     = (const float*)d_in[0];
    const float* feature = (const float*)d_in[1];
    const float* new_xyz = (const float*)d_in[2];
    const int*   idx     = (const int*)  d_in[3];
    const float* weight  = (const float*)d_in[4];
    const float* conv_w  = (const float*)d_in[5];
    const float* conv_b  = (const float*)d_in[6];
    const float* mlp_w0  = (const float*)d_in[7];
    const float* mlp_b0  = (const float*)d_in[8];
    const float* mlp_w1  = (const float*)d_in[9];
    const float* mlp_b1  = (const float*)d_in[10];
    float* out = (float*)d_out;

    (void)in_sizes; (void)n_in; (void)out_size;

    static bool attr_done = false;
    if (!attr_done) {
        cudaFuncSetAttribute(gather_kernel,
                             cudaFuncAttributeMaxDynamicSharedMemorySize,
                             NPTS * 8);
        attr_done = true;
    }

    prep_kernel<<<(BB * NPTS + NTHR - 1) / NTHR, NTHR>>>(
        xyz, feature, new_xyz, conv_w, mlp_w0, mlp_w1, out);

    // grid: b(2) x mtile(256) x chhalf(2), chhalf fastest
    gather_kernel<<<BB * (MM / PT) * 2, GTHR, NPTS * 8>>>(idx, weight);

    compute_kernel<<<(BB * MM) / PTS, NTHR>>>(
        new_xyz, conv_b, mlp_b0, mlp_b1, out);
}